// round 6
// baseline (speedup 1.0000x reference)
#include <cuda_runtime.h>
#include <cuda_bf16.h>

// ---------------- problem constants (shapes are fixed) ----------------
#define N_NODES  100000
#define F_IN     128
#define HID      64
#define N_EDGES  1600000
#define N_GRAPHS 1000
#define PER_G    100
#define TOPK     30
#define KSZ      3
#define CONV_O   32
#define CONV_T   28          // TOPK - KSZ + 1
#define FLAT     896         // CONV_O * CONV_T
#define SCAN_B   1024
#define NB_SCAN  98          // ceil(N_NODES / 1024)

// ---------------- scratch (device globals: alloc-guard safe) ----------
__device__ int   g_deg[N_NODES];
__device__ int   g_off[N_NODES];
__device__ int   g_cur[N_NODES];
__device__ int   g_bsum[NB_SCAN];
__device__ int   g_csr[N_EDGES];
__device__ float g_mean[(size_t)N_NODES * F_IN];   // also reused as N x 64
__device__ float g_h0[(size_t)N_NODES * HID];
__device__ float g_h1[(size_t)N_NODES * HID];
__device__ float g_topk[(size_t)N_GRAPHS * TOPK * HID];

// ---------------- CSR build --------------------------------------------
__global__ void k_zero_deg() {
    int i = blockIdx.x * blockDim.x + threadIdx.x;
    if (i < N_NODES) g_deg[i] = 0;
}

__global__ void k_count(const int* __restrict__ dst) {
    int e = blockIdx.x * blockDim.x + threadIdx.x;
    if (e < N_EDGES) atomicAdd(&g_deg[dst[e]], 1);
}

__global__ void k_scan1() {
    __shared__ int s[SCAN_B];
    int i = blockIdx.x * SCAN_B + threadIdx.x;
    int v = (i < N_NODES) ? g_deg[i] : 0;
    s[threadIdx.x] = v;
    __syncthreads();
    for (int d = 1; d < SCAN_B; d <<= 1) {
        int t = (threadIdx.x >= d) ? s[threadIdx.x - d] : 0;
        __syncthreads();
        s[threadIdx.x] += t;
        __syncthreads();
    }
    if (i < N_NODES) g_off[i] = s[threadIdx.x] - v;  // exclusive
    if (threadIdx.x == SCAN_B - 1) g_bsum[blockIdx.x] = s[SCAN_B - 1];
}

__global__ void k_scan2() {   // tiny serial scan of 98 block sums
    if (threadIdx.x == 0 && blockIdx.x == 0) {
        int acc = 0;
        for (int b = 0; b < NB_SCAN; ++b) { int t = g_bsum[b]; g_bsum[b] = acc; acc += t; }
    }
}

__global__ void k_scan3() {
    int i = blockIdx.x * blockDim.x + threadIdx.x;
    if (i < N_NODES) {
        int o = g_off[i] + g_bsum[i >> 10];
        g_off[i] = o;
        g_cur[i] = o;
    }
}

__global__ void k_fill_csr(const int* __restrict__ src, const int* __restrict__ dst) {
    int e = blockIdx.x * blockDim.x + threadIdx.x;
    if (e < N_EDGES) {
        int pos = atomicAdd(&g_cur[dst[e]], 1);
        g_csr[pos] = src[e];
    }
}

// ---------------- mean aggregation: one warp per node ------------------
template<int F>
__global__ void __launch_bounds__(256) k_agg(const float* __restrict__ in,
                                             float* __restrict__ out) {
    int node = (blockIdx.x * blockDim.x + threadIdx.x) >> 5;
    int lane = threadIdx.x & 31;
    if (node >= N_NODES) return;
    int beg = g_off[node];
    int d   = g_deg[node];
    float acc[F / 32];
#pragma unroll
    for (int i = 0; i < F / 32; ++i) acc[i] = 0.f;
    for (int e = beg; e < beg + d; ++e) {
        int s = g_csr[e];
        const float* r = in + (size_t)s * F;
#pragma unroll
        for (int i = 0; i < F / 32; ++i) acc[i] += __ldg(r + lane + 32 * i);
    }
    float inv = 1.f / (float)max(d, 1);
#pragma unroll
    for (int i = 0; i < F / 32; ++i)
        out[(size_t)node * F + lane + 32 * i] = acc[i] * inv;
}

// ---------------- fused two-input SAGE GEMM ----------------------------
// C[n, :64] = relu(A1 @ W1 + A2 @ W2 + bias)    A: [N, F], W: [F, 64]
// 64x64 tile, 256 threads, 4x4 microtile, KT=16.
template<int F>
__global__ void __launch_bounds__(256) k_sage_gemm(
    const float* __restrict__ A1, const float* __restrict__ A2,
    const float* __restrict__ W1, const float* __restrict__ W2,
    const float* __restrict__ bias, float* __restrict__ C) {
    __shared__ float As[16][68];
    __shared__ float Bs[16][68];
    const int tid = threadIdx.x;
    const int tx = tid & 15, ty = tid >> 4;
    const int m0 = blockIdx.x * 64;

    float acc[4][4];
#pragma unroll
    for (int i = 0; i < 4; ++i)
#pragma unroll
        for (int j = 0; j < 4; ++j) acc[i][j] = 0.f;

    const int lr  = tid >> 2;          // A-load row 0..63
    const int lc4 = (tid & 3) << 2;    // A-load k offset (x4)
    const int bkk = tid >> 4;          // B-load k row 0..15
    const int bc  = (tid & 15) << 2;   // B-load col (x4)

#pragma unroll
    for (int pass = 0; pass < 2; ++pass) {
        const float* A = pass ? A2 : A1;
        const float* W = pass ? W2 : W1;
        for (int kt = 0; kt < F; kt += 16) {
            float4 va = make_float4(0.f, 0.f, 0.f, 0.f);
            int row = m0 + lr;
            if (row < N_NODES)
                va = *reinterpret_cast<const float4*>(A + (size_t)row * F + kt + lc4);
            float4 vb = *reinterpret_cast<const float4*>(W + (size_t)(kt + bkk) * 64 + bc);
            __syncthreads();
            As[lc4 + 0][lr] = va.x; As[lc4 + 1][lr] = va.y;
            As[lc4 + 2][lr] = va.z; As[lc4 + 3][lr] = va.w;
            Bs[bkk][bc + 0] = vb.x; Bs[bkk][bc + 1] = vb.y;
            Bs[bkk][bc + 2] = vb.z; Bs[bkk][bc + 3] = vb.w;
            __syncthreads();
#pragma unroll
            for (int k = 0; k < 16; ++k) {
                float a[4], b[4];
#pragma unroll
                for (int i = 0; i < 4; ++i) a[i] = As[k][ty * 4 + i];
#pragma unroll
                for (int j = 0; j < 4; ++j) b[j] = Bs[k][tx * 4 + j];
#pragma unroll
                for (int i = 0; i < 4; ++i)
#pragma unroll
                    for (int j = 0; j < 4; ++j) acc[i][j] += a[i] * b[j];
            }
        }
    }

#pragma unroll
    for (int i = 0; i < 4; ++i) {
        int row = m0 + ty * 4 + i;
        if (row >= N_NODES) continue;
#pragma unroll
        for (int j = 0; j < 4; ++j) {
            int col = tx * 4 + j;
            float v = acc[i][j] + __ldg(bias + col);
            C[(size_t)row * 64 + col] = v > 0.f ? v : 0.f;
        }
    }
}

// ---------------- sort-pool: stable descending top-k -------------------
__global__ void __launch_bounds__(128) k_sortpool(const float* __restrict__ h) {
    int g = blockIdx.x;
    __shared__ float key[PER_G];
    __shared__ int   sel[TOPK];
    int t = threadIdx.x;
    if (t < PER_G) key[t] = h[((size_t)(g * PER_G + t)) * HID + (HID - 1)];
    __syncthreads();
    if (t < PER_G) {
        float ki = key[t];
        int r = 0;
#pragma unroll 4
        for (int j = 0; j < PER_G; ++j) {
            float kj = key[j];
            r += (kj > ki) || (kj == ki && j < t);   // stable descending
        }
        if (r < TOPK) sel[r] = t;
    }
    __syncthreads();
    for (int idx = t; idx < TOPK * HID; idx += 128) {
        int slot = idx >> 6, f = idx & 63;
        g_topk[(size_t)g * (TOPK * HID) + idx] =
            h[((size_t)(g * PER_G + sel[slot])) * HID + f];
    }
}

// ---------------- conv1d + MLP head, one block per graph ---------------
__global__ void __launch_bounds__(256) k_head(
    const float* __restrict__ cw, const float* __restrict__ cb,
    const float* __restrict__ w1, const float* __restrict__ bb1,
    const float* __restrict__ w2, const float* __restrict__ bb2,
    float* __restrict__ out) {
    int g = blockIdx.x, tid = threadIdx.x;
    __shared__ float tk[TOPK * HID];            // 7680 B
    __shared__ float cws[CONV_O * HID * KSZ];   // 24 KB
    __shared__ float yf[FLAT];
    __shared__ float ps[256];
    __shared__ float z[HID];

    for (int i = tid; i < TOPK * HID; i += 256) tk[i] = g_topk[(size_t)g * (TOPK * HID) + i];
    for (int i = tid; i < CONV_O * HID * KSZ; i += 256) cws[i] = cw[i];
    __syncthreads();

    // conv1d VALID + relu:  y[o,t] = relu(cb[o] + sum_{i,s} tk[t+s, i] * cw[o,i,s])
    for (int idx = tid; idx < FLAT; idx += 256) {
        int o = idx / CONV_T, t = idx % CONV_T;
        float acc = __ldg(cb + o);
        const float* cwo = cws + o * (HID * KSZ);
#pragma unroll 8
        for (int i = 0; i < HID; ++i) {
            const float* cwp = cwo + i * KSZ;
            acc += tk[(t + 0) * HID + i] * cwp[0];
            acc += tk[(t + 1) * HID + i] * cwp[1];
            acc += tk[(t + 2) * HID + i] * cwp[2];
        }
        yf[idx] = acc > 0.f ? acc : 0.f;
    }
    __syncthreads();

    // dense 896 -> 64, relu. 4 partial chunks of 224 per output.
    {
        int hh = tid & 63, chunk = tid >> 6;
        float acc = 0.f;
        int f0 = chunk * 224, f1 = f0 + 224;
        for (int f = f0; f < f1; ++f) acc += yf[f] * __ldg(w1 + (size_t)f * 64 + hh);
        ps[tid] = acc;
    }
    __syncthreads();
    if (tid < 64) {
        float v = ps[tid] + ps[tid + 64] + ps[tid + 128] + ps[tid + 192] + __ldg(bb1 + tid);
        z[tid] = v > 0.f ? v : 0.f;
    }
    __syncthreads();

    if (tid == 0) {
        float s = __ldg(bb2);
#pragma unroll
        for (int h = 0; h < HID; ++h) s += z[h] * __ldg(w2 + h);
        out[g] = s;
    }
}

// ---------------- launch ------------------------------------------------
extern "C" void kernel_launch(void* const* d_in, const int* in_sizes, int n_in,
                              void* d_out, int out_size) {
    const float* x   = (const float*)d_in[0];
    const int*   src = (const int*)d_in[1];
    const int*   dst = (const int*)d_in[2];
    // d_in[3] = num_graphs (constant 1000, ignored)
    const float* wl1 = (const float*)d_in[4];
    const float* wr1 = (const float*)d_in[5];
    const float* b1  = (const float*)d_in[6];
    const float* wl2 = (const float*)d_in[7];
    const float* wr2 = (const float*)d_in[8];
    const float* b2  = (const float*)d_in[9];
    const float* wl3 = (const float*)d_in[10];
    const float* wr3 = (const float*)d_in[11];
    const float* b3  = (const float*)d_in[12];
    const float* cw  = (const float*)d_in[13];
    const float* cb  = (const float*)d_in[14];
    const float* w1  = (const float*)d_in[15];
    const float* bb1 = (const float*)d_in[16];
    const float* w2  = (const float*)d_in[17];
    const float* bb2 = (const float*)d_in[18];
    float* out = (float*)d_out;

    // symbols resolved at link time; raw device-global access from kernels.
    // ---- CSR build
    k_zero_deg<<<(N_NODES + 255) / 256, 256>>>();
    k_count<<<(N_EDGES + 255) / 256, 256>>>(dst);
    k_scan1<<<NB_SCAN, SCAN_B>>>();
    k_scan2<<<1, 32>>>();
    k_scan3<<<(N_NODES + 255) / 256, 256>>>();
    k_fill_csr<<<(N_EDGES + 255) / 256, 256>>>(src, dst);

    // pointers to device globals via a tiny helper kernel is unnecessary;
    // kernels reference the globals directly. Grab raw pointers for GEMM I/O:
    float *p_mean, *p_h0, *p_h1;
    cudaGetSymbolAddress((void**)&p_mean, g_mean);
    cudaGetSymbolAddress((void**)&p_h0, g_h0);
    cudaGetSymbolAddress((void**)&p_h1, g_h1);

    const int aggBlocks = (N_NODES * 32 + 255) / 256;   // one warp per node
    const int gemmBlocks = (N_NODES + 63) / 64;

    // ---- layer 1 (F=128)
    k_agg<128><<<aggBlocks, 256>>>(x, p_mean);
    k_sage_gemm<128><<<gemmBlocks, 256>>>(p_mean, x, wl1, wr1, b1, p_h0);
    // ---- layer 2 (F=64)
    k_agg<64><<<aggBlocks, 256>>>(p_h0, p_mean);
    k_sage_gemm<64><<<gemmBlocks, 256>>>(p_mean, p_h0, wl2, wr2, b2, p_h1);
    // ---- layer 3 (F=64)
    k_agg<64><<<aggBlocks, 256>>>(p_h1, p_mean);
    k_sage_gemm<64><<<gemmBlocks, 256>>>(p_mean, p_h1, wl3, wr3, b3, p_h0);

    // ---- sort-pool + head
    k_sortpool<<<N_GRAPHS, 128>>>(p_h0);
    k_head<<<N_GRAPHS, 256>>>(cw, cb, w1, bb1, w2, bb2, out);
}